// round 6
// baseline (speedup 1.0000x reference)
#include <cuda_runtime.h>
#include <cuda_fp16.h>
#include <cstdint>

#define BATCH   65536
#define DIM     128
#define NPROTO  512
#define ODIM    8
#define MTILE   128
#define NCHUNK  64
#define NCHUNKS 8
#define NTHREADS 256

#define ASTRIDE 272
#define ATILE   (MTILE * ASTRIDE)      // 34816
#define BTILE   (NCHUNK * ASTRIDE)     // 17408

#define SM_BIAS 0                      // 512 f32
#define SM_NRM  2048                   // 128 f32 (per-row bound B_r)
#define SM_A    2560
#define SM_B    (SM_A + ATILE)         // 37376
#define SM_RED  SM_A                   // reduction arrays reuse A after mainloop
#define SMEM_TOTAL (SM_B + 2 * BTILE)  // 72192 -> 2 CTAs/SM

__device__ __align__(16) __half g_h[NPROTO * DIM];   // fp16 high split of w=r^2*p, [p][d]
__device__ __align__(16) float  g_wf[NPROTO * DIM];  // exact fp32 w, [p][d]
__device__ float g_bias[NPROTO];
__device__ int   g_maxMw = 0;   // float bits: max_p ||w_p - H_p||
__device__ int   g_maxW  = 0;   // float bits: max_p ||w_p||
__device__ int   g_flag[BATCH];

// ---------------- helpers ----------------
__device__ __forceinline__ uint32_t smem_u32(const void* p) {
    uint32_t a;
    asm("{ .reg .u64 t; cvta.to.shared.u64 t, %1; cvt.u32.u64 %0, t; }" : "=r"(a) : "l"(p));
    return a;
}
__device__ __forceinline__ void ldsm4(uint32_t* r, uint32_t a) {
    asm volatile("ldmatrix.sync.aligned.m8n8.x4.shared.b16 {%0,%1,%2,%3}, [%4];"
                 : "=r"(r[0]), "=r"(r[1]), "=r"(r[2]), "=r"(r[3]) : "r"(a));
}
__device__ __forceinline__ void mma16816(float* d, const uint32_t* a, const uint32_t* b) {
    asm volatile(
        "mma.sync.aligned.m16n8k16.row.col.f32.f16.f16.f32 "
        "{%0,%1,%2,%3}, {%4,%5,%6,%7}, {%8,%9}, {%0,%1,%2,%3};"
        : "+f"(d[0]), "+f"(d[1]), "+f"(d[2]), "+f"(d[3])
        : "r"(a[0]), "r"(a[1]), "r"(a[2]), "r"(a[3]), "r"(b[0]), "r"(b[1]));
}
__device__ __forceinline__ void cp_async16(uint32_t dst, const void* src) {
    asm volatile("cp.async.cg.shared.global [%0], [%1], 16;" :: "r"(dst), "l"(src));
}

// ---------------------------------------------------------------------------
// Prep: H = fp16(w), exact w, bias, and global norm maxima for the bound.
// ---------------------------------------------------------------------------
__global__ void prep_kernel(const float* __restrict__ protos,
                            const float* __restrict__ relevance) {
    int p = blockIdx.x;          // 512
    int d = threadIdx.x;         // 128
    float r  = relevance[d];
    float pv = protos[p * DIM + d];
    float w  = r * r * pv;

    __half h  = __float2half_rn(w);
    float  Mw = w - __half2float(h);
    g_h[p * DIM + d]  = h;
    g_wf[p * DIM + d] = w;

    float sb = w * pv, sm = Mw * Mw, sw = w * w;
    __shared__ float r0[4], r1[4], r2[4];
    #pragma unroll
    for (int off = 16; off > 0; off >>= 1) {
        sb += __shfl_down_sync(0xffffffffu, sb, off);
        sm += __shfl_down_sync(0xffffffffu, sm, off);
        sw += __shfl_down_sync(0xffffffffu, sw, off);
    }
    if ((d & 31) == 0) { r0[d >> 5] = sb; r1[d >> 5] = sm; r2[d >> 5] = sw; }
    __syncthreads();
    if (d == 0) {
        g_bias[p] = -0.5f * (r0[0] + r0[1] + r0[2] + r0[3]);
        float nm = sqrtf(r1[0] + r1[1] + r1[2] + r1[3]) * 1.0001f;
        float nw = sqrtf(r2[0] + r2[1] + r2[2] + r2[3]) * 1.0001f;
        atomicMax(&g_maxMw, __float_as_int(nm));
        atomicMax(&g_maxW,  __float_as_int(nw));
    }
}

// ---------------------------------------------------------------------------
// Phase 1: hh-only fp16 GEMM + top-2 tracking + certainty test.
//   256 threads, 2 CTAs/SM, warps 4M x 2N, warp tile 32x32, chunk N=64.
// ---------------------------------------------------------------------------
extern __shared__ char smem[];

__global__ void __launch_bounds__(NTHREADS, 2)
grlvq_phase1(const float* __restrict__ x,
             const float* __restrict__ proto_out,
             float* __restrict__ out) {
    const uint32_t sb = smem_u32(smem);
    const int tid  = threadIdx.x;
    const int wid  = tid >> 5;
    const int lane = tid & 31;
    const int row0 = blockIdx.x * MTILE;
    const int wm = (wid & 3) * 32;
    const int wn = (wid >> 2) * 32;

    for (int i = tid; i < NPROTO; i += NTHREADS)
        ((float*)(smem + SM_BIAS))[i] = g_bias[i];

    #define ISSUE_B(c, buf)                                                        \
        do {                                                                       \
            for (int i = tid; i < 1024; i += NTHREADS) {                           \
                int rr = i >> 4, q = i & 15;                                       \
                const void* src = &g_h[(size_t)((c) * NCHUNK + rr) * DIM + q * 8]; \
                uint32_t dst = sb + SM_B + (buf) * BTILE + rr * ASTRIDE + q * 16;  \
                cp_async16(dst, src);                                              \
            }                                                                      \
            asm volatile("cp.async.commit_group;" ::: "memory");                   \
        } while (0)

    ISSUE_B(0, 0);
    ISSUE_B(1, 1);

    // ---- A: load x tile, fp16-split, keep only h; accumulate row norms ----
    {
        const int r  = tid >> 1;
        const int cb = (tid & 1) * 64;
        const float4* xr = (const float4*)(x + (size_t)(row0 + r) * DIM + cb);
        float sx2 = 0.0f, sm2 = 0.0f;
        #pragma unroll
        for (int g = 0; g < 8; g++) {
            float4 v0 = xr[g * 2], v1 = xr[g * 2 + 1];
            float xv[8] = {v0.x, v0.y, v0.z, v0.w, v1.x, v1.y, v1.z, v1.w};
            uint32_t hh[4];
            #pragma unroll
            for (int q = 0; q < 4; q++) {
                float a0 = xv[2 * q], a1 = xv[2 * q + 1];
                __half h0 = __float2half_rn(a0), h1 = __float2half_rn(a1);
                float m0 = a0 - __half2float(h0), m1 = a1 - __half2float(h1);
                sx2 += a0 * a0 + a1 * a1;
                sm2 += m0 * m0 + m1 * m1;
                hh[q] = ((uint32_t)__half_as_ushort(h1) << 16) | __half_as_ushort(h0);
            }
            uint32_t off = (uint32_t)r * ASTRIDE + (uint32_t)(cb + g * 8) * 2;
            *(uint4*)(smem + SM_A + off) = make_uint4(hh[0], hh[1], hh[2], hh[3]);
        }
        sx2 += __shfl_xor_sync(0xffffffffu, sx2, 1);
        sm2 += __shfl_xor_sync(0xffffffffu, sm2, 1);
        if ((tid & 1) == 0) {
            float maxMw = __int_as_float(g_maxMw);
            float maxW  = __int_as_float(g_maxW);
            ((float*)(smem + SM_NRM))[r] =
                1.0002f * sqrtf(sx2) * maxMw + 1.0002f * sqrtf(sm2) * maxW + 0.01f;
        }
    }

    // per-thread top-2 per row slot (4 slots)
    float v1s[4], v2s[4];
    int   i1s[4];
    #pragma unroll
    for (int i = 0; i < 4; i++) { v1s[i] = -3.4e38f; v2s[i] = -3.4e38f; i1s[i] = 0; }

    const uint32_t a_row = (uint32_t)(wm + (lane & 15));
    const uint32_t a_kh  = (uint32_t)(lane >> 4) * 16;
    const uint32_t b_row = (uint32_t)(wn + ((lane >> 4) & 1) * 8 + (lane & 7));
    const uint32_t b_kh  = (uint32_t)((lane >> 3) & 1) * 16;

    #define INS(v, c, s) { if ((v) > v2s[s]) { \
        if ((v) > v1s[s]) { v2s[s] = v1s[s]; v1s[s] = (v); i1s[s] = (c); } \
        else v2s[s] = (v); } }

    for (int c = 0; c < NCHUNKS; c++) {
        asm volatile("cp.async.wait_group 1;" ::: "memory");
        __syncthreads();
        const uint32_t bbase = sb + SM_B + (c & 1) * BTILE;

        float acc[2][4][4];
        #pragma unroll
        for (int mt = 0; mt < 2; mt++)
            #pragma unroll
            for (int nt = 0; nt < 4; nt++)
                #pragma unroll
                for (int j = 0; j < 4; j++) acc[mt][nt][j] = 0.0f;

        #pragma unroll
        for (int kk = 0; kk < 8; kk++) {
            uint32_t af[2][4], bf[2][4];
            #pragma unroll
            for (int mt = 0; mt < 2; mt++)
                ldsm4(af[mt], sb + SM_A + (a_row + mt * 16) * ASTRIDE + kk * 32 + a_kh);
            #pragma unroll
            for (int np = 0; np < 2; np++)
                ldsm4(bf[np], bbase + (b_row + np * 16) * ASTRIDE + kk * 32 + b_kh);
            #pragma unroll
            for (int mt = 0; mt < 2; mt++)
                #pragma unroll
                for (int nt = 0; nt < 4; nt++)
                    mma16816(acc[mt][nt], af[mt], &bf[nt >> 1][(nt & 1) * 2]);
        }

        const float* bias_s = (const float*)(smem + SM_BIAS);
        #pragma unroll
        for (int mt = 0; mt < 2; mt++) {
            #pragma unroll
            for (int nt = 0; nt < 4; nt++) {
                const int col = c * NCHUNK + wn + nt * 8 + (lane & 3) * 2;
                float b0 = bias_s[col], b1 = bias_s[col + 1];
                float v0 = acc[mt][nt][0] + b0;
                float v1 = acc[mt][nt][1] + b1;
                float v2 = acc[mt][nt][2] + b0;
                float v3 = acc[mt][nt][3] + b1;
                INS(v0, col,     mt * 2);
                INS(v1, col + 1, mt * 2);
                INS(v2, col,     mt * 2 + 1);
                INS(v3, col + 1, mt * 2 + 1);
            }
        }

        __syncthreads();
        if (c + 2 < NCHUNKS) ISSUE_B(c + 2, c & 1);
    }

    // ---- cross-thread top-2 merge: 8 owners per row ----
    float* rv1 = (float*)(smem + SM_RED);
    int*   ri1 = (int*)(smem + SM_RED + 4096);
    float* rv2 = (float*)(smem + SM_RED + 8192);
    const int slot = ((wid >> 2) << 2) | (lane & 3);
    #pragma unroll
    for (int sl = 0; sl < 4; sl++) {
        int row = wm + (sl >> 1) * 16 + (sl & 1) * 8 + (lane >> 2);
        rv1[row * 8 + slot] = v1s[sl];
        ri1[row * 8 + slot] = i1s[sl];
        rv2[row * 8 + slot] = v2s[sl];
    }
    __syncthreads();

    if (tid < MTILE) {
        float b1 = -3.4e38f, b2 = -3.4e38f;
        int   bi = 0;
        #pragma unroll
        for (int j = 0; j < 8; j++) {
            float v = rv1[tid * 8 + j];
            int  ix = ri1[tid * 8 + j];
            if (v > b1) { b2 = b1; b1 = v; bi = ix; }
            else if (v > b2) b2 = v;
        }
        #pragma unroll
        for (int j = 0; j < 8; j++) {
            float v = rv2[tid * 8 + j];
            if (v > b2) b2 = v;
        }
        float Br = ((const float*)(smem + SM_NRM))[tid];
        g_flag[row0 + tid] = (b1 - b2 > 2.0f * Br) ? 0 : 1;

        const float4* po = (const float4*)proto_out;
        float4* o = (float4*)(out + (size_t)(row0 + tid) * ODIM);
        o[0] = po[bi * 2];
        o[1] = po[bi * 2 + 1];
    }
}

// ---------------------------------------------------------------------------
// Phase 2: exact fp32 rescore for flagged rows (first-min-index semantics).
// ---------------------------------------------------------------------------
__global__ void __launch_bounds__(128)
grlvq_phase2(const float* __restrict__ x,
             const float* __restrict__ proto_out,
             float* __restrict__ out) {
    const int tid = threadIdx.x;
    const int r0  = blockIdx.x * 128;
    __shared__ float sx[DIM];
    __shared__ float rv[128];
    __shared__ int   ri[128];

    for (int k = 0; k < 128; k++) {
        int r = r0 + k;
        if (!g_flag[r]) continue;            // uniform branch

        sx[tid] = x[(size_t)r * DIM + tid];
        __syncthreads();

        const int p0 = tid * 4;
        float a0 = 0.f, a1 = 0.f, a2 = 0.f, a3 = 0.f;
        const float4* xv4 = (const float4*)sx;
        for (int dd = 0; dd < DIM / 4; dd++) {
            float4 xv = xv4[dd];
            float4 w0 = *(const float4*)&g_wf[(size_t)(p0 + 0) * DIM + dd * 4];
            float4 w1 = *(const float4*)&g_wf[(size_t)(p0 + 1) * DIM + dd * 4];
            float4 w2 = *(const float4*)&g_wf[(size_t)(p0 + 2) * DIM + dd * 4];
            float4 w3 = *(const float4*)&g_wf[(size_t)(p0 + 3) * DIM + dd * 4];
            a0 += xv.x * w0.x + xv.y * w0.y + xv.z * w0.z + xv.w * w0.w;
            a1 += xv.x * w1.x + xv.y * w1.y + xv.z * w1.z + xv.w * w1.w;
            a2 += xv.x * w2.x + xv.y * w2.y + xv.z * w2.z + xv.w * w2.w;
            a3 += xv.x * w3.x + xv.y * w3.y + xv.z * w3.z + xv.w * w3.w;
        }
        float s[4] = {a0 + g_bias[p0], a1 + g_bias[p0 + 1],
                      a2 + g_bias[p0 + 2], a3 + g_bias[p0 + 3]};
        float bv = s[0]; int bi = p0;
        #pragma unroll
        for (int j = 1; j < 4; j++)
            if (s[j] > bv) { bv = s[j]; bi = p0 + j; }   // ascending j: '>' keeps first
        rv[tid] = bv; ri[tid] = bi;
        __syncthreads();

        for (int sft = 64; sft > 0; sft >>= 1) {
            if (tid < sft) {
                float v = rv[tid + sft]; int ix = ri[tid + sft];
                if (v > rv[tid] || (v == rv[tid] && ix < ri[tid])) {
                    rv[tid] = v; ri[tid] = ix;
                }
            }
            __syncthreads();
        }
        if (tid == 0) {
            int bidx = ri[0];
            const float4* po = (const float4*)proto_out;
            float4* o = (float4*)(out + (size_t)r * ODIM);
            o[0] = po[bidx * 2];
            o[1] = po[bidx * 2 + 1];
        }
        __syncthreads();
    }
}

// ---------------------------------------------------------------------------
extern "C" void kernel_launch(void* const* d_in, const int* in_sizes, int n_in,
                              void* d_out, int out_size) {
    const float* x         = (const float*)d_in[0];  // [65536,128]
    const float* protos    = (const float*)d_in[1];  // [512,128]
    const float* proto_out = (const float*)d_in[2];  // [512,8]
    const float* relevance = (const float*)d_in[3];  // [128]
    float* out = (float*)d_out;                      // [65536,8]

    prep_kernel<<<NPROTO, DIM>>>(protos, relevance);

    cudaFuncSetAttribute(grlvq_phase1,
                         cudaFuncAttributeMaxDynamicSharedMemorySize, SMEM_TOTAL);
    grlvq_phase1<<<BATCH / MTILE, NTHREADS, SMEM_TOTAL>>>(x, proto_out, out);

    grlvq_phase2<<<BATCH / 128, 128>>>(x, proto_out, out);
}

// round 7
// speedup vs baseline: 2.7965x; 2.7965x over previous
#include <cuda_runtime.h>
#include <cuda_fp16.h>
#include <cstdint>

#define BATCH   65536
#define DIM     128
#define NPROTO  512
#define ODIM    8
#define MTILE   128
#define NCHUNK  64
#define NCHUNKS 8
#define NTHREADS 256

#define ASTRIDE 272
#define ATILE   (MTILE * ASTRIDE)
#define BTILE   (NCHUNK * ASTRIDE)

#define SM_BIAS 0
#define SM_NRM  2048
#define SM_A    2560
#define SM_B    (SM_A + ATILE)
#define SM_RED  SM_A
#define SMEM_TOTAL (SM_B + 2 * BTILE)   // 72192

#define P2ROWS   32
#define P2BLOCKS 256
#define P2SMEM   ((4096 + 16384 + 512 + 512 + 512) * 4)   // 88064

__device__ __align__(16) __half g_h[NPROTO * DIM];   // fp16 high split of w
__device__ __align__(16) float  g_wf[NPROTO * DIM];  // exact fp32 w
__device__ float g_bias[NPROTO];
__device__ int   g_maxMw = 0;
__device__ int   g_maxW  = 0;
__device__ int   g_nflag;
__device__ int   g_list[BATCH];

// ---------------- helpers ----------------
__device__ __forceinline__ uint32_t smem_u32(const void* p) {
    uint32_t a;
    asm("{ .reg .u64 t; cvta.to.shared.u64 t, %1; cvt.u32.u64 %0, t; }" : "=r"(a) : "l"(p));
    return a;
}
__device__ __forceinline__ void ldsm4(uint32_t* r, uint32_t a) {
    asm volatile("ldmatrix.sync.aligned.m8n8.x4.shared.b16 {%0,%1,%2,%3}, [%4];"
                 : "=r"(r[0]), "=r"(r[1]), "=r"(r[2]), "=r"(r[3]) : "r"(a));
}
__device__ __forceinline__ void mma16816(float* d, const uint32_t* a, const uint32_t* b) {
    asm volatile(
        "mma.sync.aligned.m16n8k16.row.col.f32.f16.f16.f32 "
        "{%0,%1,%2,%3}, {%4,%5,%6,%7}, {%8,%9}, {%0,%1,%2,%3};"
        : "+f"(d[0]), "+f"(d[1]), "+f"(d[2]), "+f"(d[3])
        : "r"(a[0]), "r"(a[1]), "r"(a[2]), "r"(a[3]), "r"(b[0]), "r"(b[1]));
}
__device__ __forceinline__ void cp_async16(uint32_t dst, const void* src) {
    asm volatile("cp.async.cg.shared.global [%0], [%1], 16;" :: "r"(dst), "l"(src));
}

// ---------------------------------------------------------------------------
// Prep: H = fp16(w), exact w, bias, norm maxima; reset flag counter.
// ---------------------------------------------------------------------------
__global__ void prep_kernel(const float* __restrict__ protos,
                            const float* __restrict__ relevance) {
    int p = blockIdx.x;
    int d = threadIdx.x;
    if (p == 0 && d == 0) g_nflag = 0;

    float r  = relevance[d];
    float pv = protos[p * DIM + d];
    float w  = r * r * pv;

    __half h  = __float2half_rn(w);
    float  Mw = w - __half2float(h);
    g_h[p * DIM + d]  = h;
    g_wf[p * DIM + d] = w;

    float sb = w * pv, sm = Mw * Mw, sw = w * w;
    __shared__ float r0[4], r1[4], r2[4];
    #pragma unroll
    for (int off = 16; off > 0; off >>= 1) {
        sb += __shfl_down_sync(0xffffffffu, sb, off);
        sm += __shfl_down_sync(0xffffffffu, sm, off);
        sw += __shfl_down_sync(0xffffffffu, sw, off);
    }
    if ((d & 31) == 0) { r0[d >> 5] = sb; r1[d >> 5] = sm; r2[d >> 5] = sw; }
    __syncthreads();
    if (d == 0) {
        g_bias[p] = -0.5f * (r0[0] + r0[1] + r0[2] + r0[3]);
        float nm = sqrtf(r1[0] + r1[1] + r1[2] + r1[3]) * 1.0001f;
        float nw = sqrtf(r2[0] + r2[1] + r2[2] + r2[3]) * 1.0001f;
        atomicMax(&g_maxMw, __float_as_int(nm));
        atomicMax(&g_maxW,  __float_as_int(nw));
    }
}

// ---------------------------------------------------------------------------
// Phase 1: hh-only fp16 GEMM + top-2 + certainty test + flagged-list append.
// ---------------------------------------------------------------------------
extern __shared__ char smem[];

__global__ void __launch_bounds__(NTHREADS, 2)
grlvq_phase1(const float* __restrict__ x,
             const float* __restrict__ proto_out,
             float* __restrict__ out) {
    const uint32_t sb = smem_u32(smem);
    const int tid  = threadIdx.x;
    const int wid  = tid >> 5;
    const int lane = tid & 31;
    const int row0 = blockIdx.x * MTILE;
    const int wm = (wid & 3) * 32;
    const int wn = (wid >> 2) * 32;

    for (int i = tid; i < NPROTO; i += NTHREADS)
        ((float*)(smem + SM_BIAS))[i] = g_bias[i];

    #define ISSUE_B(c, buf)                                                        \
        do {                                                                       \
            for (int i = tid; i < 1024; i += NTHREADS) {                           \
                int rr = i >> 4, q = i & 15;                                       \
                const void* src = &g_h[(size_t)((c) * NCHUNK + rr) * DIM + q * 8]; \
                uint32_t dst = sb + SM_B + (buf) * BTILE + rr * ASTRIDE + q * 16;  \
                cp_async16(dst, src);                                              \
            }                                                                      \
            asm volatile("cp.async.commit_group;" ::: "memory");                   \
        } while (0)

    ISSUE_B(0, 0);
    ISSUE_B(1, 1);

    {
        const int r  = tid >> 1;
        const int cb = (tid & 1) * 64;
        const float4* xr = (const float4*)(x + (size_t)(row0 + r) * DIM + cb);
        float sx2 = 0.0f, sm2 = 0.0f;
        #pragma unroll
        for (int g = 0; g < 8; g++) {
            float4 v0 = xr[g * 2], v1 = xr[g * 2 + 1];
            float xv[8] = {v0.x, v0.y, v0.z, v0.w, v1.x, v1.y, v1.z, v1.w};
            uint32_t hh[4];
            #pragma unroll
            for (int q = 0; q < 4; q++) {
                float a0 = xv[2 * q], a1 = xv[2 * q + 1];
                __half h0 = __float2half_rn(a0), h1 = __float2half_rn(a1);
                float m0 = a0 - __half2float(h0), m1 = a1 - __half2float(h1);
                sx2 += a0 * a0 + a1 * a1;
                sm2 += m0 * m0 + m1 * m1;
                hh[q] = ((uint32_t)__half_as_ushort(h1) << 16) | __half_as_ushort(h0);
            }
            uint32_t off = (uint32_t)r * ASTRIDE + (uint32_t)(cb + g * 8) * 2;
            *(uint4*)(smem + SM_A + off) = make_uint4(hh[0], hh[1], hh[2], hh[3]);
        }
        sx2 += __shfl_xor_sync(0xffffffffu, sx2, 1);
        sm2 += __shfl_xor_sync(0xffffffffu, sm2, 1);
        if ((tid & 1) == 0) {
            float maxMw = __int_as_float(g_maxMw);
            float maxW  = __int_as_float(g_maxW);
            ((float*)(smem + SM_NRM))[r] =
                1.0002f * sqrtf(sx2) * maxMw + 1.0002f * sqrtf(sm2) * maxW + 0.01f;
        }
    }

    float v1s[4], v2s[4];
    int   i1s[4];
    #pragma unroll
    for (int i = 0; i < 4; i++) { v1s[i] = -3.4e38f; v2s[i] = -3.4e38f; i1s[i] = 0; }

    const uint32_t a_row = (uint32_t)(wm + (lane & 15));
    const uint32_t a_kh  = (uint32_t)(lane >> 4) * 16;
    const uint32_t b_row = (uint32_t)(wn + ((lane >> 4) & 1) * 8 + (lane & 7));
    const uint32_t b_kh  = (uint32_t)((lane >> 3) & 1) * 16;

    #define INS(v, c, s) { if ((v) > v2s[s]) { \
        if ((v) > v1s[s]) { v2s[s] = v1s[s]; v1s[s] = (v); i1s[s] = (c); } \
        else v2s[s] = (v); } }

    for (int c = 0; c < NCHUNKS; c++) {
        asm volatile("cp.async.wait_group 1;" ::: "memory");
        __syncthreads();
        const uint32_t bbase = sb + SM_B + (c & 1) * BTILE;

        float acc[2][4][4];
        #pragma unroll
        for (int mt = 0; mt < 2; mt++)
            #pragma unroll
            for (int nt = 0; nt < 4; nt++)
                #pragma unroll
                for (int j = 0; j < 4; j++) acc[mt][nt][j] = 0.0f;

        #pragma unroll
        for (int kk = 0; kk < 8; kk++) {
            uint32_t af[2][4], bf[2][4];
            #pragma unroll
            for (int mt = 0; mt < 2; mt++)
                ldsm4(af[mt], sb + SM_A + (a_row + mt * 16) * ASTRIDE + kk * 32 + a_kh);
            #pragma unroll
            for (int np = 0; np < 2; np++)
                ldsm4(bf[np], bbase + (b_row + np * 16) * ASTRIDE + kk * 32 + b_kh);
            #pragma unroll
            for (int mt = 0; mt < 2; mt++)
                #pragma unroll
                for (int nt = 0; nt < 4; nt++)
                    mma16816(acc[mt][nt], af[mt], &bf[nt >> 1][(nt & 1) * 2]);
        }

        const float* bias_s = (const float*)(smem + SM_BIAS);
        #pragma unroll
        for (int mt = 0; mt < 2; mt++) {
            #pragma unroll
            for (int nt = 0; nt < 4; nt++) {
                const int col = c * NCHUNK + wn + nt * 8 + (lane & 3) * 2;
                float b0 = bias_s[col], b1 = bias_s[col + 1];
                float v0 = acc[mt][nt][0] + b0;
                float v1 = acc[mt][nt][1] + b1;
                float v2 = acc[mt][nt][2] + b0;
                float v3 = acc[mt][nt][3] + b1;
                INS(v0, col,     mt * 2);
                INS(v1, col + 1, mt * 2);
                INS(v2, col,     mt * 2 + 1);
                INS(v3, col + 1, mt * 2 + 1);
            }
        }

        __syncthreads();
        if (c + 2 < NCHUNKS) ISSUE_B(c + 2, c & 1);
    }

    float* rv1 = (float*)(smem + SM_RED);
    int*   ri1 = (int*)(smem + SM_RED + 4096);
    float* rv2 = (float*)(smem + SM_RED + 8192);
    const int slot = ((wid >> 2) << 2) | (lane & 3);
    #pragma unroll
    for (int sl = 0; sl < 4; sl++) {
        int row = wm + (sl >> 1) * 16 + (sl & 1) * 8 + (lane >> 2);
        rv1[row * 8 + slot] = v1s[sl];
        ri1[row * 8 + slot] = i1s[sl];
        rv2[row * 8 + slot] = v2s[sl];
    }
    __syncthreads();

    if (tid < MTILE) {
        float b1 = -3.4e38f, b2 = -3.4e38f;
        int   bi = 0;
        #pragma unroll
        for (int j = 0; j < 8; j++) {
            float v = rv1[tid * 8 + j];
            int  ix = ri1[tid * 8 + j];
            if (v > b1) { b2 = b1; b1 = v; bi = ix; }
            else if (v > b2) b2 = v;
        }
        #pragma unroll
        for (int j = 0; j < 8; j++) {
            float v = rv2[tid * 8 + j];
            if (v > b2) b2 = v;
        }
        float Br = ((const float*)(smem + SM_NRM))[tid];
        if (!(b1 - b2 > 2.0f * Br)) {
            int k = atomicAdd(&g_nflag, 1);
            g_list[k] = row0 + tid;
        }
        const float4* po = (const float4*)proto_out;
        float4* o = (float4*)(out + (size_t)(row0 + tid) * ODIM);
        o[0] = po[bi * 2];
        o[1] = po[bi * 2 + 1];
    }
}

// ---------------------------------------------------------------------------
// Phase 2: batched exact fp32 rescore of flagged rows (32 rows per block).
// ---------------------------------------------------------------------------
extern __shared__ float s2[];

__global__ void __launch_bounds__(256)
grlvq_phase2(const float* __restrict__ x,
             const float* __restrict__ proto_out,
             float* __restrict__ out) {
    float* sx    = s2;                     // 32 x 128
    float* sw    = s2 + 4096;              // [128 dims][128 protos]
    float* sbias = s2 + 4096 + 16384;      // 512
    float* rv    = sbias + 512;            // 32 x 16
    int*   ri    = (int*)(rv + 512);       // 32 x 16

    const int tid = threadIdx.x;
    const int nflag = g_nflag;
    for (int i = tid; i < NPROTO; i += 256) sbias[i] = g_bias[i];

    const int tr = tid >> 4;       // 0..15 -> rows {tr, tr+16}
    const int tp = tid & 15;       // protos tp*8 .. tp*8+7 per chunk

    for (int base = blockIdx.x * P2ROWS; base < nflag; base += P2BLOCKS * P2ROWS) {
        __syncthreads();           // protect sx/rv reuse across iterations
        const int nr = min(P2ROWS, nflag - base);

        for (int i = tid; i < P2ROWS * 32; i += 256) {
            int r = i >> 5, q = i & 31;
            if (r < nr) {
                int row = g_list[base + r];
                ((float4*)sx)[i] = ((const float4*)(x + (size_t)row * DIM))[q];
            }
        }

        float bv0 = -3.4e38f, bv1 = -3.4e38f;
        int   bi0 = 0, bi1 = 0;

        for (int c = 0; c < 4; c++) {
            __syncthreads();
            {   // transpose-load w chunk: sw[d][p]
                int pr = tid >> 1;
                int d0 = (tid & 1) * 64;
                const float4* wsrc =
                    (const float4*)&g_wf[(size_t)(c * 128 + pr) * DIM + d0];
                #pragma unroll
                for (int q = 0; q < 16; q++) {
                    float4 v = wsrc[q];
                    int d = d0 + q * 4;
                    sw[(d + 0) * 128 + pr] = v.x;
                    sw[(d + 1) * 128 + pr] = v.y;
                    sw[(d + 2) * 128 + pr] = v.z;
                    sw[(d + 3) * 128 + pr] = v.w;
                }
            }
            __syncthreads();

            float acc[2][8];
            #pragma unroll
            for (int a = 0; a < 2; a++)
                #pragma unroll
                for (int j = 0; j < 8; j++) acc[a][j] = 0.0f;

            #pragma unroll 8
            for (int dd = 0; dd < 128; dd++) {
                float x0 = sx[tr * 128 + dd];
                float x1 = sx[(tr + 16) * 128 + dd];
                const float4* wp = (const float4*)&sw[dd * 128 + tp * 8];
                float4 w0 = wp[0], w1 = wp[1];
                acc[0][0] += x0 * w0.x; acc[0][1] += x0 * w0.y;
                acc[0][2] += x0 * w0.z; acc[0][3] += x0 * w0.w;
                acc[0][4] += x0 * w1.x; acc[0][5] += x0 * w1.y;
                acc[0][6] += x0 * w1.z; acc[0][7] += x0 * w1.w;
                acc[1][0] += x1 * w0.x; acc[1][1] += x1 * w0.y;
                acc[1][2] += x1 * w0.z; acc[1][3] += x1 * w0.w;
                acc[1][4] += x1 * w1.x; acc[1][5] += x1 * w1.y;
                acc[1][6] += x1 * w1.z; acc[1][7] += x1 * w1.w;
            }

            #pragma unroll
            for (int j = 0; j < 8; j++) {       // ascending p: '>' keeps first
                int p = c * 128 + tp * 8 + j;
                float s0 = acc[0][j] + sbias[p];
                float s1 = acc[1][j] + sbias[p];
                if (s0 > bv0) { bv0 = s0; bi0 = p; }
                if (s1 > bv1) { bv1 = s1; bi1 = p; }
            }
        }

        rv[tr * 16 + tp] = bv0;        ri[tr * 16 + tp] = bi0;
        rv[(tr + 16) * 16 + tp] = bv1; ri[(tr + 16) * 16 + tp] = bi1;
        __syncthreads();

        if (tid < nr) {
            float bv = rv[tid * 16];
            int   bi = ri[tid * 16];
            #pragma unroll
            for (int j = 1; j < 16; j++) {
                float v  = rv[tid * 16 + j];
                int   ix = ri[tid * 16 + j];
                if (v > bv || (v == bv && ix < bi)) { bv = v; bi = ix; }
            }
            int row = g_list[base + tid];
            const float4* po = (const float4*)proto_out;
            float4* o = (float4*)(out + (size_t)row * ODIM);
            o[0] = po[bi * 2];
            o[1] = po[bi * 2 + 1];
        }
    }
}

// ---------------------------------------------------------------------------
extern "C" void kernel_launch(void* const* d_in, const int* in_sizes, int n_in,
                              void* d_out, int out_size) {
    const float* x         = (const float*)d_in[0];
    const float* protos    = (const float*)d_in[1];
    const float* proto_out = (const float*)d_in[2];
    const float* relevance = (const float*)d_in[3];
    float* out = (float*)d_out;

    prep_kernel<<<NPROTO, DIM>>>(protos, relevance);

    cudaFuncSetAttribute(grlvq_phase1,
                         cudaFuncAttributeMaxDynamicSharedMemorySize, SMEM_TOTAL);
    grlvq_phase1<<<BATCH / MTILE, NTHREADS, SMEM_TOTAL>>>(x, proto_out, out);

    cudaFuncSetAttribute(grlvq_phase2,
                         cudaFuncAttributeMaxDynamicSharedMemorySize, P2SMEM);
    grlvq_phase2<<<P2BLOCKS, 256, P2SMEM>>>(x, proto_out, out);
}